// round 9
// baseline (speedup 1.0000x reference)
#include <cuda_runtime.h>
#include <cuda_bf16.h>
#include <cstdint>

#define C_CLASSES 6625
#define D_DIM     96
#define NTHREADS  256
#define NWARPS    (NTHREADS / 32)
#define MAX_ROWS  8192
#define EPSV      1e-7f
#define INFV      1e11f

// Per-(row, warp) argmax candidates: .x = float bits of max, .y = index.
__device__ uint2 g_partial[MAX_ROWS * NWARPS];

// clip() applied to the masked-out zeros contributes (C-1)*EPS exactly.
__global__ void cl_init_out(float* out) {
    out[0] = (float)(C_CLASSES - 1) * EPSV;
}

// Tournament compare: independent fmax tree, one dependent compare vs best,
// index recovered only on the rare update; x,y,z,w tested in order keeps
// first-occurrence within the quad.
__device__ __forceinline__ void cmp4t(float4 q, int base, float& best, int& bidx) {
    float m = fmaxf(fmaxf(q.x, q.y), fmaxf(q.z, q.w));
    if (m > best) {
        best = m;
        bidx = (q.x == m) ? base
             : (q.y == m) ? base + 1
             : (q.z == m) ? base + 2
             :              base + 3;
    }
}

// ─── Phase 1: barrier-free streaming argmax scan, per-warp candidate out ───
__global__ __launch_bounds__(NTHREADS, 8)
void scan_kernel(const float* __restrict__ predicts, int N)
{
    const int n    = blockIdx.x;
    const int tid  = threadIdx.x;
    const int lane = tid & 31;
    const int warp = tid >> 5;
    const float* row = predicts + (size_t)n * C_CLASSES;

    // Row stride 26500 B is only 4B-aligned -> scalar prologue, then LDG.128.
    const int mis = ((int)((uintptr_t)row >> 2)) & 3;
    const int p   = (4 - mis) & 3;
    const int nv  = (C_CLASSES - p) >> 2;               // >= 1655
    const int tail_start = p + (nv << 2);
    const float4* vrow = (const float4*)(row + p);

    float best = -3.402823466e38f;
    int   bidx = C_CLASSES;

    // Pipelined scan: <=4 float4s live (regs <= 32), MLP ~4.
    // tid + i*256 for i<6 is always < nv (1535 < 1655).
    float4 a0 = __ldg(vrow + tid);
    float4 a1 = __ldg(vrow + tid + 1 * NTHREADS);
    float4 a2 = __ldg(vrow + tid + 2 * NTHREADS);
    float4 a3 = __ldg(vrow + tid + 3 * NTHREADS);

    cmp4t(a0, p + (tid << 2),                    best, bidx);
    float4 b0 = __ldg(vrow + tid + 4 * NTHREADS);
    cmp4t(a1, p + ((tid + 1 * NTHREADS) << 2),   best, bidx);
    float4 b1 = __ldg(vrow + tid + 5 * NTHREADS);
    cmp4t(a2, p + ((tid + 2 * NTHREADS) << 2),   best, bidx);
    const int v6 = tid + 6 * NTHREADS;
    float4 b2 = (v6 < nv) ? __ldg(vrow + v6)
                          : make_float4(-3.4e38f, -3.4e38f, -3.4e38f, -3.4e38f);
    cmp4t(a3, p + ((tid + 3 * NTHREADS) << 2),   best, bidx);
    cmp4t(b0, p + ((tid + 4 * NTHREADS) << 2),   best, bidx);
    cmp4t(b1, p + ((tid + 5 * NTHREADS) << 2),   best, bidx);
    if (v6 < nv) cmp4t(b2, p + (v6 << 2),        best, bidx);

    // Scalar prologue (indices below all vector indices: needs tie-break).
    if (tid < p) {
        float v = __ldg(row + tid);
        if (v > best || (v == best && tid < bidx)) { best = v; bidx = tid; }
    }
    // Scalar tail (indices above all vector indices: strict > suffices).
    {
        int t = tail_start + tid;
        if (t < C_CLASSES) {
            float v = __ldg(row + t);
            if (v > best) { best = v; bidx = t; }
        }
    }

    // Warp (val, idx) reduce, min-idx tie-break; then ONE 8B store. No smem,
    // no __syncthreads -- warps retire independently.
    #pragma unroll
    for (int off = 16; off > 0; off >>= 1) {
        float ov = __shfl_down_sync(0xffffffffu, best, off);
        int   oi = __shfl_down_sync(0xffffffffu, bidx, off);
        if (ov > best || (ov == best && oi < bidx)) { best = ov; bidx = oi; }
    }
    if (lane == 0)
        g_partial[n * NWARPS + warp] = make_uint2(__float_as_uint(best), (unsigned)bidx);
}

// ─── Phase 2: warp-per-row finish (candidate reduce + distance + atomic) ───
__global__ __launch_bounds__(NTHREADS, 8)
void finish_kernel(const float* __restrict__ features,  // [N, 96]
                   const float* __restrict__ centers,   // [6625, 96]
                   float* __restrict__ out,
                   int N)
{
    const int warp = threadIdx.x >> 5;
    const int lane = threadIdx.x & 31;
    const int n    = blockIdx.x * NWARPS + warp;
    if (n >= N) return;

    float best = -3.402823466e38f;
    int   bidx = 0x7fffffff;
    if (lane < NWARPS) {
        uint2 pv = g_partial[n * NWARPS + lane];
        best = __uint_as_float(pv.x);
        bidx = (int)pv.y;
    }
    // Lexicographic (max val, min idx) over 8 lanes: associative, so the
    // interleaved per-warp index sets reduce to jnp.argmax first-occurrence.
    #pragma unroll
    for (int off = NWARPS / 2; off > 0; off >>= 1) {
        float ov = __shfl_down_sync(0xffffffffu, best, off);
        int   oi = __shfl_down_sync(0xffffffffu, bidx, off);
        if (ov > best || (ov == best && oi < bidx)) { best = ov; bidx = oi; }
    }
    const int label = __shfl_sync(0xffffffffu, bidx, 0);

    // Squared distance over D=96: 24 lanes x float4 (16B-aligned rows).
    float part = 0.0f;
    if (lane < D_DIM / 4) {
        float4 f = __ldg((const float4*)(features + (size_t)n * D_DIM) + lane);
        float4 c = __ldg((const float4*)(centers + (size_t)label * D_DIM) + lane);
        float dx = f.x - c.x, dy = f.y - c.y, dz = f.z - c.z, dw = f.w - c.w;
        part = dx * dx + dy * dy + dz * dz + dw * dw;
    }
    #pragma unroll
    for (int off = 16; off > 0; off >>= 1)
        part += __shfl_down_sync(0xffffffffu, part, off);

    if (lane == 0) {
        float dist = fminf(fmaxf(part, EPSV), INFV);
        atomicAdd(out, dist / (float)N);
    }
}

extern "C" void kernel_launch(void* const* d_in, const int* in_sizes, int n_in,
                              void* d_out, int out_size) {
    const float* features = (const float*)d_in[0];  // [B,T,D] fp32
    const float* predicts = (const float*)d_in[1];  // [B,T,C] fp32
    const float* centers  = (const float*)d_in[2];  // [C,D]   fp32
    float* out = (float*)d_out;

    int N = in_sizes[0] / D_DIM;  // B*T = 8192
    if (N > MAX_ROWS) N = MAX_ROWS;

    cl_init_out<<<1, 1>>>(out);
    scan_kernel<<<N, NTHREADS>>>(predicts, N);
    finish_kernel<<<(N + NWARPS - 1) / NWARPS, NTHREADS>>>(features, centers, out, N);
}

// round 11
// speedup vs baseline: 1.1285x; 1.1285x over previous
#include <cuda_runtime.h>
#include <cuda_bf16.h>
#include <cstdint>

#define C_CLASSES 6625
#define D_DIM     96
#define NTHREADS  256
#define NWARPS    (NTHREADS / 32)
#define NSLOTS    6            // cp.async-staged float4s per thread (always in range)
#define EPSV      1e-7f
#define INFV      1e11f

// clip() applied to the masked-out zeros contributes (C-1)*EPS exactly.
__global__ void cl_init_out(float* out) {
    out[0] = (float)(C_CLASSES - 1) * EPSV;
}

__device__ __forceinline__ void cp16(uint32_t dst_smem, const void* src) {
    asm volatile("cp.async.cg.shared.global [%0], [%1], 16;"
                 :: "r"(dst_smem), "l"(src) : "memory");
}
__device__ __forceinline__ void cp_commit() {
    asm volatile("cp.async.commit_group;" ::: "memory");
}
template <int N>
__device__ __forceinline__ void cp_wait() {
    asm volatile("cp.async.wait_group %0;" :: "n"(N) : "memory");
}

// Tournament compare: independent fmax tree, one dependent compare vs best,
// index recovered only on the rare update; x,y,z,w in order keeps
// first-occurrence within the quad.
__device__ __forceinline__ void cmp4t(float4 q, int base, float& best, int& bidx) {
    float m = fmaxf(fmaxf(q.x, q.y), fmaxf(q.z, q.w));
    if (m > best) {
        best = m;
        bidx = (q.x == m) ? base
             : (q.y == m) ? base + 1
             : (q.z == m) ? base + 2
             :              base + 3;
    }
}

__global__ __launch_bounds__(NTHREADS, 8)
void center_loss_kernel(const float* __restrict__ features,  // [N, 96]
                        const float* __restrict__ predicts,  // [N, 6625]
                        const float* __restrict__ centers,   // [6625, 96]
                        float* __restrict__ out,
                        int N)
{
    // Per-thread private staging: thread t only ever touches stage[s][t],
    // so cp.async completion ordering (per-thread wait_group) is sufficient —
    // no __syncthreads needed for the staging.
    __shared__ float4 stage[NSLOTS][NTHREADS];           // 24 KB

    const int n   = blockIdx.x;
    const int tid = threadIdx.x;
    const float* row = predicts + (size_t)n * C_CLASSES;

    // Row stride 26500 B is only 4B-aligned -> scalar prologue, then 16B ops.
    const int mis = ((int)((uintptr_t)row >> 2)) & 3;
    const int p   = (4 - mis) & 3;
    const int nv  = (C_CLASSES - p) >> 2;                // 1655 or 1656
    const int tail_start = p + (nv << 2);
    const float4* vrow = (const float4*)(row + p);

    // Issue ALL staged loads in one uninterrupted burst (register-free MLP=6).
    const uint32_t sbase = (uint32_t)__cvta_generic_to_shared(&stage[0][tid]);
    cp16(sbase,                         vrow + tid);
    cp16(sbase + 1 * NTHREADS * 16,     vrow + tid + 1 * NTHREADS);
    cp16(sbase + 2 * NTHREADS * 16,     vrow + tid + 2 * NTHREADS);
    cp_commit();                                          // group A: slots 0-2
    cp16(sbase + 3 * NTHREADS * 16,     vrow + tid + 3 * NTHREADS);
    cp16(sbase + 4 * NTHREADS * 16,     vrow + tid + 4 * NTHREADS);
    cp16(sbase + 5 * NTHREADS * 16,     vrow + tid + 5 * NTHREADS);
    cp_commit();                                          // group B: slots 3-5

    // Overlap the straggler loads with the in-flight copies.
    const int v6 = tid + 6 * NTHREADS;                    // 1536..1791
    const bool has6 = v6 < nv;
    float4 q6;
    if (has6) q6 = __ldg(vrow + v6);
    const int t = tail_start + tid;
    const bool hast = t < C_CLASSES;
    float tv = hast ? __ldg(row + t) : -3.402823466e38f;
    float pv = (tid < p) ? __ldg(row + tid) : -3.402823466e38f;

    float best = -3.402823466e38f;
    int   bidx = C_CLASSES;

    cp_wait<1>();                                         // group A landed
    cmp4t(stage[0][tid], p + (tid << 2),                  best, bidx);
    cmp4t(stage[1][tid], p + ((tid + 1 * NTHREADS) << 2), best, bidx);
    cmp4t(stage[2][tid], p + ((tid + 2 * NTHREADS) << 2), best, bidx);
    cp_wait<0>();                                         // group B landed
    cmp4t(stage[3][tid], p + ((tid + 3 * NTHREADS) << 2), best, bidx);
    cmp4t(stage[4][tid], p + ((tid + 4 * NTHREADS) << 2), best, bidx);
    cmp4t(stage[5][tid], p + ((tid + 5 * NTHREADS) << 2), best, bidx);
    if (has6) cmp4t(q6, p + (v6 << 2),                    best, bidx);

    // Scalar prologue (indices below all vector indices: needs tie-break).
    if (tid < p) {
        if (pv > best || (pv == best && tid < bidx)) { best = pv; bidx = tid; }
    }
    // Scalar tail (indices above all vector indices: strict > suffices).
    if (hast && tv > best) { best = tv; bidx = t; }

    // Warp (val, idx) reduce, min-idx tie-break (jnp.argmax first occurrence).
    #pragma unroll
    for (int off = 16; off > 0; off >>= 1) {
        float ov = __shfl_down_sync(0xffffffffu, best, off);
        int   oi = __shfl_down_sync(0xffffffffu, bidx, off);
        if (ov > best || (ov == best && oi < bidx)) { best = ov; bidx = oi; }
    }

    __shared__ float swv[NWARPS];
    __shared__ int   swi[NWARPS];
    __shared__ int   slabel;
    if ((tid & 31) == 0) { swv[tid >> 5] = best; swi[tid >> 5] = bidx; }
    __syncthreads();
    if (tid == 0) {
        float bv = swv[0]; int bi = swi[0];
        #pragma unroll
        for (int w = 1; w < NWARPS; w++) {
            if (swv[w] > bv || (swv[w] == bv && swi[w] < bi)) { bv = swv[w]; bi = swi[w]; }
        }
        slabel = bi;
    }
    __syncthreads();

    // Squared distance over D=96: warp 0 only, 24 lanes x float4, shfl reduce.
    if (tid < 32) {
        const int label = slabel;
        float part = 0.0f;
        if (tid < D_DIM / 4) {
            float4 f = __ldg((const float4*)(features + (size_t)n * D_DIM) + tid);
            float4 c = __ldg((const float4*)(centers + (size_t)label * D_DIM) + tid);
            float dx = f.x - c.x, dy = f.y - c.y, dz = f.z - c.z, dw = f.w - c.w;
            part = dx * dx + dy * dy + dz * dz + dw * dw;
        }
        #pragma unroll
        for (int off = 16; off > 0; off >>= 1)
            part += __shfl_down_sync(0xffffffffu, part, off);
        if (tid == 0) {
            float dist = fminf(fmaxf(part, EPSV), INFV);
            atomicAdd(out, dist / (float)N);
        }
    }
}

extern "C" void kernel_launch(void* const* d_in, const int* in_sizes, int n_in,
                              void* d_out, int out_size) {
    const float* features = (const float*)d_in[0];  // [B,T,D] fp32
    const float* predicts = (const float*)d_in[1];  // [B,T,C] fp32
    const float* centers  = (const float*)d_in[2];  // [C,D]   fp32
    float* out = (float*)d_out;

    const int N = in_sizes[0] / D_DIM;  // B*T = 8192

    cl_init_out<<<1, 1>>>(out);
    center_loss_kernel<<<N, NTHREADS>>>(features, predicts, centers, out, N);
}

// round 13
// speedup vs baseline: 1.2547x; 1.1118x over previous
#include <cuda_runtime.h>
#include <cuda_bf16.h>
#include <cstdint>

#define C_CLASSES  6625
#define ROW_BYTES  (C_CLASSES * 4)      // 26500, only 4B-aligned
#define CP_BYTES   26496                // 1656*16: bulk-copy size, always in-bounds
#define SMEM_F     (CP_BYTES / 4)       // 6624 floats staged
#define D_DIM      96
#define NTHREADS   256
#define NWARPS     (NTHREADS / 32)
#define EPSV       1e-7f
#define INFV       1e11f

// clip() applied to the masked-out zeros contributes (C-1)*EPS exactly.
__global__ void cl_init_out(float* out) {
    out[0] = (float)(C_CLASSES - 1) * EPSV;
}

// Tournament compare: independent fmax tree, one dependent compare vs best;
// x,y,z,w tested in order keeps first-occurrence within the quad.
__device__ __forceinline__ void cmp4t(float4 q, int base, float& best, int& bidx) {
    float m = fmaxf(fmaxf(q.x, q.y), fmaxf(q.z, q.w));
    if (m > best) {
        best = m;
        bidx = (q.x == m) ? base
             : (q.y == m) ? base + 1
             : (q.z == m) ? base + 2
             :              base + 3;
    }
}

__global__ __launch_bounds__(NTHREADS, 8)
void center_loss_kernel(const float* __restrict__ features,  // [N, 96]
                        const float* __restrict__ predicts,  // [N, 6625]
                        const float* __restrict__ centers,   // [6625, 96]
                        float* __restrict__ out,
                        int N)
{
    __shared__ alignas(16) float sbuf[SMEM_F];           // 25.9 KB row stage
    __shared__ alignas(8) unsigned long long mbar;
    __shared__ float swv[NWARPS];
    __shared__ int   swi[NWARPS];
    __shared__ int   slabel;

    const int n   = blockIdx.x;
    const int tid = threadIdx.x;

    // Align the bulk-copy source DOWN to 16B; 'shift' = lead floats of slack.
    const uintptr_t row_addr = (uintptr_t)predicts + (size_t)n * ROW_BYTES;
    const uintptr_t src      = row_addr & ~(uintptr_t)15;
    const int shift          = (int)((row_addr & 15) >> 2);   // 0..3
    const float* rowf        = sbuf + shift;                  // rowf[c] == row[c]
    const int n_avail        = SMEM_F - shift;                // staged elements

    const uint32_t mbar_u32 = (uint32_t)__cvta_generic_to_shared(&mbar);
    const uint32_t dst_u32  = (uint32_t)__cvta_generic_to_shared(sbuf);

    if (tid == 0)
        asm volatile("mbarrier.init.shared.b64 [%0], 1;" :: "r"(mbar_u32) : "memory");
    __syncthreads();

    if (tid == 0) {
        asm volatile("mbarrier.arrive.expect_tx.shared.b64 _, [%0], %1;"
                     :: "r"(mbar_u32), "r"((uint32_t)CP_BYTES) : "memory");
        // ONE bulk async copy for the whole row: engine-driven DRAM stream,
        // zero issue/register coupling with the compute warps.
        asm volatile("cp.async.bulk.shared::cta.global.mbarrier::complete_tx::bytes "
                     "[%0], [%1], %2, [%3];"
                     :: "r"(dst_u32), "l"((const void*)src),
                        "r"((uint32_t)CP_BYTES), "r"(mbar_u32) : "memory");
    }

    // The last shift+1 elements (c in [n_avail, 6625)) are not staged: fetch
    // them from gmem while the bulk copy is in flight.
    float gval = -3.402823466e38f;
    int   gc   = n_avail + tid;                    // tid<4 covers 1..4 elems
    if (tid < C_CLASSES - n_avail)
        gval = __ldg((const float*)row_addr + gc);

    // Wait for the staged row (acquire orders the LDS reads below).
    {
        uint32_t done = 0;
        while (!done) {
            asm volatile(
                "{\n\t.reg .pred p;\n\t"
                "mbarrier.try_wait.parity.acquire.cta.shared::cta.b64 p, [%1], %2, 0x989680;\n\t"
                "selp.b32 %0, 1, 0, p;\n\t}"
                : "=r"(done) : "r"(mbar_u32), "r"(0u) : "memory");
        }
    }

    // Scan from smem.  q = scalar prologue so rowf+q is 16B-aligned.
    const int q   = (4 - shift) & 3;
    const int nvv = (n_avail - q) >> 2;            // float4 count
    const float4* vrow = (const float4*)(rowf + q);

    float best = -3.402823466e38f;
    int   bidx = C_CLASSES;

    #pragma unroll
    for (int i = 0; i < 7; i++) {                  // ceil(nvv/256) == 7
        int v = tid + i * NTHREADS;
        if (v < nvv) {
            float4 qv = vrow[v];                   // LDS.128, conflict-free
            cmp4t(qv, q + (v << 2), best, bidx);
        }
    }
    // Scalar prologue (indices below all vector indices: needs tie-break).
    if (tid < q) {
        float v = rowf[tid];
        if (v > best || (v == best && tid < bidx)) { best = v; bidx = tid; }
    }
    // Staged scalar tail (indices above vector body: strict > suffices).
    {
        int c = q + (nvv << 2) + tid;
        if (c < n_avail) {
            float v = rowf[c];
            if (v > best) { best = v; bidx = c; }
        }
    }
    // Gmem tail (highest indices: strict > suffices).
    if (tid < C_CLASSES - n_avail && gval > best) { best = gval; bidx = gc; }

    // Warp (val, idx) reduce, min-idx tie-break (jnp.argmax first occurrence).
    #pragma unroll
    for (int off = 16; off > 0; off >>= 1) {
        float ov = __shfl_down_sync(0xffffffffu, best, off);
        int   oi = __shfl_down_sync(0xffffffffu, bidx, off);
        if (ov > best || (ov == best && oi < bidx)) { best = ov; bidx = oi; }
    }
    if ((tid & 31) == 0) { swv[tid >> 5] = best; swi[tid >> 5] = bidx; }
    __syncthreads();
    if (tid == 0) {
        float bv = swv[0]; int bi = swi[0];
        #pragma unroll
        for (int w = 1; w < NWARPS; w++) {
            if (swv[w] > bv || (swv[w] == bv && swi[w] < bi)) { bv = swv[w]; bi = swi[w]; }
        }
        slabel = bi;
    }
    __syncthreads();

    // Squared distance over D=96: warp 0 only, 24 lanes x float4, shfl reduce.
    if (tid < 32) {
        const int label = slabel;
        float part = 0.0f;
        if (tid < D_DIM / 4) {
            float4 f = __ldg((const float4*)(features + (size_t)n * D_DIM) + tid);
            float4 c = __ldg((const float4*)(centers + (size_t)label * D_DIM) + tid);
            float dx = f.x - c.x, dy = f.y - c.y, dz = f.z - c.z, dw = f.w - c.w;
            part = dx * dx + dy * dy + dz * dz + dw * dw;
        }
        #pragma unroll
        for (int off = 16; off > 0; off >>= 1)
            part += __shfl_down_sync(0xffffffffu, part, off);
        if (tid == 0) {
            float dist = fminf(fmaxf(part, EPSV), INFV);
            atomicAdd(out, dist / (float)N);
        }
    }
}

extern "C" void kernel_launch(void* const* d_in, const int* in_sizes, int n_in,
                              void* d_out, int out_size) {
    const float* features = (const float*)d_in[0];  // [B,T,D] fp32
    const float* predicts = (const float*)d_in[1];  // [B,T,C] fp32
    const float* centers  = (const float*)d_in[2];  // [C,D]   fp32
    float* out = (float*)d_out;

    const int N = in_sizes[0] / D_DIM;  // B*T = 8192

    cl_init_out<<<1, 1>>>(out);
    center_loss_kernel<<<N, NTHREADS>>>(features, predicts, centers, out, N);
}